// round 1
// baseline (speedup 1.0000x reference)
#include <cuda_runtime.h>
#include <math.h>

#define BB 32
#define SS 512
#define DD 768
#define KK 3
#define TWOD 1536

// ---------------- device scratch (no allocs allowed) ----------------
__device__ __align__(16) float g_WeffT[KK][TWOD];   // W_eff transposed: [k][d]
__device__ float g_beff[KK];
__device__ __align__(16) float g_logits[BB * SS * KK];

// ---------------- kernel A: W_eff = W_cnn @ W_dense, b_eff ----------------
// one warp per row of W_cnn (1536 rows) + one extra warp for b_eff
__global__ void weff_kernel(const float* __restrict__ Wc,
                            const float* __restrict__ Wd,
                            const float* __restrict__ bc,
                            const float* __restrict__ bd) {
    int gw = (blockIdx.x * blockDim.x + threadIdx.x) >> 5;
    int lane = threadIdx.x & 31;
    if (gw < TWOD) {
        const float* row = Wc + (size_t)gw * DD;
        float a0 = 0.f, a1 = 0.f, a2 = 0.f;
        for (int f = lane; f < DD; f += 32) {
            float w = row[f];
            a0 = fmaf(w, Wd[f * 3 + 0], a0);
            a1 = fmaf(w, Wd[f * 3 + 1], a1);
            a2 = fmaf(w, Wd[f * 3 + 2], a2);
        }
        #pragma unroll
        for (int o = 16; o; o >>= 1) {
            a0 += __shfl_xor_sync(0xffffffffu, a0, o);
            a1 += __shfl_xor_sync(0xffffffffu, a1, o);
            a2 += __shfl_xor_sync(0xffffffffu, a2, o);
        }
        if (lane == 0) {
            g_WeffT[0][gw] = a0;
            g_WeffT[1][gw] = a1;
            g_WeffT[2][gw] = a2;
        }
    } else if (gw == TWOD) {
        float a0 = 0.f, a1 = 0.f, a2 = 0.f;
        for (int f = lane; f < DD; f += 32) {
            float w = bc[f];
            a0 = fmaf(w, Wd[f * 3 + 0], a0);
            a1 = fmaf(w, Wd[f * 3 + 1], a1);
            a2 = fmaf(w, Wd[f * 3 + 2], a2);
        }
        #pragma unroll
        for (int o = 16; o; o >>= 1) {
            a0 += __shfl_xor_sync(0xffffffffu, a0, o);
            a1 += __shfl_xor_sync(0xffffffffu, a1, o);
            a2 += __shfl_xor_sync(0xffffffffu, a2, o);
        }
        if (lane == 0) {
            g_beff[0] = a0 + bd[0];
            g_beff[1] = a1 + bd[1];
            g_beff[2] = a2 + bd[2];
        }
    }
}

// ---------------- kernel B: logits[b,s,k] = x . W_eff[:,k] + b_eff[k] ----------------
// one warp per (b,s) row; vectorized float4 streaming of hidden/weights_sub
__global__ void __launch_bounds__(256) logits_kernel(const float* __restrict__ hidden,
                                                     const float* __restrict__ wsub) {
    int gw = (blockIdx.x * blockDim.x + threadIdx.x) >> 5;  // row id in [0, B*S)
    int lane = threadIdx.x & 31;
    if (gw >= BB * SS) return;

    const float4* h4 = (const float4*)(hidden + (size_t)gw * DD);
    const float4* s4 = (const float4*)(wsub + (size_t)gw * DD);
    const float4* e0 = (const float4*)g_WeffT[0];
    const float4* e1 = (const float4*)g_WeffT[1];
    const float4* e2 = (const float4*)g_WeffT[2];

    float a0 = 0.f, a1 = 0.f, a2 = 0.f;
    #pragma unroll
    for (int it = 0; it < 6; it++) {             // 6*32*4 = 768 elems
        int i = it * 32 + lane;
        float4 x = h4[i];
        float4 w0 = e0[i], w1 = e1[i], w2 = e2[i];
        a0 = fmaf(x.x, w0.x, fmaf(x.y, w0.y, fmaf(x.z, w0.z, fmaf(x.w, w0.w, a0))));
        a1 = fmaf(x.x, w1.x, fmaf(x.y, w1.y, fmaf(x.z, w1.z, fmaf(x.w, w1.w, a1))));
        a2 = fmaf(x.x, w2.x, fmaf(x.y, w2.y, fmaf(x.z, w2.z, fmaf(x.w, w2.w, a2))));
    }
    #pragma unroll
    for (int it = 0; it < 6; it++) {
        int i = it * 32 + lane;
        int j = i + DD / 4;                       // second half of W_eff rows
        float4 x = s4[i];
        float4 w0 = e0[j], w1 = e1[j], w2 = e2[j];
        a0 = fmaf(x.x, w0.x, fmaf(x.y, w0.y, fmaf(x.z, w0.z, fmaf(x.w, w0.w, a0))));
        a1 = fmaf(x.x, w1.x, fmaf(x.y, w1.y, fmaf(x.z, w1.z, fmaf(x.w, w1.w, a1))));
        a2 = fmaf(x.x, w2.x, fmaf(x.y, w2.y, fmaf(x.z, w2.z, fmaf(x.w, w2.w, a2))));
    }
    #pragma unroll
    for (int o = 16; o; o >>= 1) {
        a0 += __shfl_xor_sync(0xffffffffu, a0, o);
        a1 += __shfl_xor_sync(0xffffffffu, a1, o);
        a2 += __shfl_xor_sync(0xffffffffu, a2, o);
    }
    if (lane == 0) {
        float* o = g_logits + (size_t)gw * KK;
        o[0] = a0 + g_beff[0];
        o[1] = a1 + g_beff[1];
        o[2] = a2 + g_beff[2];
    }
}

// ---------------- kernel C: CRF (seq_len, fwd LSE scan, viterbi, traceback, ll) ----------------
// one block (128 threads) per batch element
__global__ void __launch_bounds__(128) crf_kernel(const float* __restrict__ trans,
                                                  const int* __restrict__ tgt,
                                                  float* __restrict__ out,
                                                  int out_size) {
    __shared__ float sh_log[SS * KK];       // 6 KB
    __shared__ int sh_tgt[SS];              // 2 KB
    __shared__ int sh_bp[SS];               // 2 KB (packed backpointers)
    __shared__ unsigned char sh_tags[SS];   // 512 B
    __shared__ int sh_seqlen;
    __shared__ float sh_lognorm, sh_unary, sh_binary;

    int b = blockIdx.x;
    int tid = threadIdx.x;
    if (tid == 0) sh_seqlen = 0;

    for (int i = tid; i < SS; i += 128) {
        sh_tgt[i] = tgt[b * SS + i];
        sh_tags[i] = 0;
    }
    const float* lg = g_logits + (size_t)b * SS * KK;
    for (int i = tid; i < SS * KK; i += 128) sh_log[i] = lg[i];
    __syncthreads();

    // seq_len = count(obj_target >= 1)
    {
        int cnt = 0;
        for (int i = tid; i < SS; i += 128) cnt += (sh_tgt[i] >= 1);
        #pragma unroll
        for (int o = 16; o; o >>= 1) cnt += __shfl_xor_sync(0xffffffffu, cnt, o);
        if ((tid & 31) == 0) atomicAdd(&sh_seqlen, cnt);
    }
    __syncthreads();
    int L = sh_seqlen;

    if (tid == 0) {
        // ---- forward log-sum-exp scan up to idx = clip(L-1, 0, S-1) ----
        float t00 = trans[0], t01 = trans[1], t02 = trans[2];
        float t10 = trans[3], t11 = trans[4], t12 = trans[5];
        float t20 = trans[6], t21 = trans[7], t22 = trans[8];
        float a0 = sh_log[0], a1 = sh_log[1], a2 = sh_log[2];
        int idx = L - 1;
        if (idx < 0) idx = 0;
        if (idx > SS - 1) idx = SS - 1;
        for (int t = 1; t <= idx; t++) {
            float l0 = sh_log[t * 3 + 0], l1 = sh_log[t * 3 + 1], l2 = sh_log[t * 3 + 2];
            float x0 = a0 + t00, x1 = a1 + t10, x2 = a2 + t20;
            float m0 = fmaxf(fmaxf(x0, x1), x2);
            float s0 = __expf(x0 - m0) + __expf(x1 - m0) + __expf(x2 - m0);
            float y0 = a0 + t01, y1 = a1 + t11, y2 = a2 + t21;
            float m1 = fmaxf(fmaxf(y0, y1), y2);
            float s1 = __expf(y0 - m1) + __expf(y1 - m1) + __expf(y2 - m1);
            float z0 = a0 + t02, z1 = a1 + t12, z2 = a2 + t22;
            float m2 = fmaxf(fmaxf(z0, z1), z2);
            float s2 = __expf(z0 - m2) + __expf(z1 - m2) + __expf(z2 - m2);
            a0 = l0 + m0 + __logf(s0);
            a1 = l1 + m1 + __logf(s1);
            a2 = l2 + m2 + __logf(s2);
        }
        float m = fmaxf(fmaxf(a0, a1), a2);
        float ln = m + __logf(__expf(a0 - m) + __expf(a1 - m) + __expf(a2 - m));
        if (L <= 0) ln = 0.0f;
        sh_lognorm = ln;
    } else if (tid == 32) {
        // ---- viterbi scan + traceback (masked steps leave alpha unchanged, bp=0) ----
        float t00 = trans[0], t01 = trans[1], t02 = trans[2];
        float t10 = trans[3], t11 = trans[4], t12 = trans[5];
        float t20 = trans[6], t21 = trans[7], t22 = trans[8];
        float a0 = sh_log[0], a1 = sh_log[1], a2 = sh_log[2];
        for (int t = 1; t < L; t++) {
            float l0 = sh_log[t * 3 + 0], l1 = sh_log[t * 3 + 1], l2 = sh_log[t * 3 + 2];
            // j = 0 (argmax over i, first-max tie-breaking like jnp.argmax)
            float x0 = a0 + t00, x1 = a1 + t10, x2 = a2 + t20;
            float bst0 = x0; int bi0 = 0;
            if (x1 > bst0) { bst0 = x1; bi0 = 1; }
            if (x2 > bst0) { bst0 = x2; bi0 = 2; }
            // j = 1
            float y0 = a0 + t01, y1 = a1 + t11, y2 = a2 + t21;
            float bst1 = y0; int bi1 = 0;
            if (y1 > bst1) { bst1 = y1; bi1 = 1; }
            if (y2 > bst1) { bst1 = y2; bi1 = 2; }
            // j = 2
            float z0 = a0 + t02, z1 = a1 + t12, z2 = a2 + t22;
            float bst2 = z0; int bi2 = 0;
            if (z1 > bst2) { bst2 = z1; bi2 = 1; }
            if (z2 > bst2) { bst2 = z2; bi2 = 2; }
            sh_bp[t] = bi0 | (bi1 << 2) | (bi2 << 4);
            a0 = l0 + bst0; a1 = l1 + bst1; a2 = l2 + bst2;
        }
        if (L > 0) {
            int tag = 0;
            float bst = a0;
            if (a1 > bst) { bst = a1; tag = 1; }
            if (a2 > bst) { bst = a2; tag = 2; }
            sh_tags[L - 1] = (unsigned char)tag;
            for (int t = L - 2; t >= 0; t--) {
                tag = (sh_bp[t + 1] >> (2 * tag)) & 3;
                sh_tags[t] = (unsigned char)tag;
            }
        }
    } else if (tid >= 64 && tid < 96) {
        // ---- unary ----
        int lane = tid - 64;
        float u = 0.f;
        for (int s = lane; s < SS; s += 32)
            if (s < L) u += sh_log[s * 3 + sh_tgt[s]];
        #pragma unroll
        for (int o = 16; o; o >>= 1) u += __shfl_xor_sync(0xffffffffu, u, o);
        if (lane == 0) sh_unary = u;
    } else if (tid >= 96) {
        // ---- binary ----
        int lane = tid - 96;
        float v = 0.f;
        for (int s = lane; s < SS - 1; s += 32)
            if (s < L - 1) v += trans[sh_tgt[s] * 3 + sh_tgt[s + 1]];
        #pragma unroll
        for (int o = 16; o; o >>= 1) v += __shfl_xor_sync(0xffffffffu, v, o);
        if (lane == 0) sh_binary = v;
    }
    __syncthreads();

    // ---- output: [tags as float (B*S)] then [log_likelihood (B)] ----
    bool has_tags = (out_size >= BB * SS);
    if (has_tags) {
        for (int s = tid; s < SS; s += 128)
            out[b * SS + s] = (float)sh_tags[s];
    }
    int ll_off = has_tags ? (BB * SS) : 0;
    if (out_size >= ll_off + BB && tid == 0) {
        out[ll_off + b] = sh_unary + sh_binary - sh_lognorm;
    }
}

// ---------------- launch ----------------
extern "C" void kernel_launch(void* const* d_in, const int* in_sizes, int n_in,
                              void* d_out, int out_size) {
    const float *hidden = nullptr, *wsub = nullptr, *Wc = nullptr, *bc = nullptr;
    const float *Wd = nullptr, *bd = nullptr, *trans = nullptr;
    const int* tgt = nullptr;

    for (int i = 0; i < n_in; i++) {
        int sz = in_sizes[i];
        if (sz == BB * SS * DD) {
            if (!hidden) hidden = (const float*)d_in[i];
            else wsub = (const float*)d_in[i];
        } else if (sz == BB * SS) {
            tgt = (const int*)d_in[i];
        } else if (sz == TWOD * DD) {
            Wc = (const float*)d_in[i];
        } else if (sz == DD) {
            bc = (const float*)d_in[i];
        } else if (sz == DD * KK) {
            Wd = (const float*)d_in[i];
        } else if (sz == KK) {
            bd = (const float*)d_in[i];
        } else if (sz == KK * KK) {
            trans = (const float*)d_in[i];
        }
    }

    // A: fold W_cnn @ W_dense -> W_eff (1537 warps)
    weff_kernel<<<193, 256>>>(Wc, Wd, bc, bd);
    // B: logits, one warp per (b,s) row: 16384 warps / 8 per block
    logits_kernel<<<(BB * SS) / 8, 256>>>(hidden, wsub);
    // C: CRF, one block per batch
    crf_kernel<<<BB, 128>>>(trans, tgt, (float*)d_out, out_size);
}

// round 2
// speedup vs baseline: 1.4417x; 1.4417x over previous
#include <cuda_runtime.h>
#include <math.h>

#define BB 32
#define SS 512
#define DD 768
#define KK 3
#define TWOD 1536

// ---------------- device scratch (no allocs allowed) ----------------
__device__ __align__(16) float g_WeffT[KK][TWOD];   // W_eff transposed: [k][d]
__device__ float g_beff[KK];
__device__ __align__(16) float g_logits[BB * SS * KK];

// ---------------- kernel A: W_eff = W_cnn @ W_dense, b_eff ----------------
// one warp per row of W_cnn (1536 rows) + one extra warp for b_eff.
// All loads vectorized float4: Wc row = 6 float4/lane, Wd rows 4f..4f+3 = 3 contiguous float4.
__global__ void __launch_bounds__(256) weff_kernel(const float* __restrict__ Wc,
                                                   const float* __restrict__ Wd,
                                                   const float* __restrict__ bc,
                                                   const float* __restrict__ bd) {
    int gw = (blockIdx.x * blockDim.x + threadIdx.x) >> 5;
    int lane = threadIdx.x & 31;
    if (gw > TWOD) return;
    const float* src = (gw < TWOD) ? (Wc + (size_t)gw * DD) : bc;
    const float4* s4 = (const float4*)src;
    const float4* wd4 = (const float4*)Wd;

    float a0 = 0.f, a1 = 0.f, a2 = 0.f;
    #pragma unroll
    for (int it = 0; it < 6; it++) {
        int i = it * 32 + lane;          // float4 index into row; f = 4*i
        float4 x  = s4[i];
        float4 wA = wd4[i * 3 + 0];      // Wd[4i+0][0..2], Wd[4i+1][0]
        float4 wB = wd4[i * 3 + 1];      // Wd[4i+1][1..2], Wd[4i+2][0..1]
        float4 wC = wd4[i * 3 + 2];      // Wd[4i+2][2], Wd[4i+3][0..2]
        a0 = fmaf(x.x, wA.x, a0); a1 = fmaf(x.x, wA.y, a1); a2 = fmaf(x.x, wA.z, a2);
        a0 = fmaf(x.y, wA.w, a0); a1 = fmaf(x.y, wB.x, a1); a2 = fmaf(x.y, wB.y, a2);
        a0 = fmaf(x.z, wB.z, a0); a1 = fmaf(x.z, wB.w, a1); a2 = fmaf(x.z, wC.x, a2);
        a0 = fmaf(x.w, wC.y, a0); a1 = fmaf(x.w, wC.z, a1); a2 = fmaf(x.w, wC.w, a2);
    }
    #pragma unroll
    for (int o = 16; o; o >>= 1) {
        a0 += __shfl_xor_sync(0xffffffffu, a0, o);
        a1 += __shfl_xor_sync(0xffffffffu, a1, o);
        a2 += __shfl_xor_sync(0xffffffffu, a2, o);
    }
    if (lane == 0) {
        if (gw < TWOD) {
            g_WeffT[0][gw] = a0;
            g_WeffT[1][gw] = a1;
            g_WeffT[2][gw] = a2;
        } else {
            g_beff[0] = a0 + bd[0];
            g_beff[1] = a1 + bd[1];
            g_beff[2] = a2 + bd[2];
        }
    }
}

// ---------------- kernel B: logits ----------------
// one warp per 4 (b,s) rows: W_eff float4s loaded once, reused for 4 x-rows.
__global__ void __launch_bounds__(256) logits_kernel(const float* __restrict__ hidden,
                                                     const float* __restrict__ wsub) {
    int gw = (blockIdx.x * blockDim.x + threadIdx.x) >> 5;   // 0..4095
    int lane = threadIdx.x & 31;
    if (gw >= (BB * SS) / 4) return;
    int r0 = gw * 4;

    const float4* e0 = (const float4*)g_WeffT[0];
    const float4* e1 = (const float4*)g_WeffT[1];
    const float4* e2 = (const float4*)g_WeffT[2];
    const float4* hp[4];
    const float4* sp[4];
    #pragma unroll
    for (int r = 0; r < 4; r++) {
        hp[r] = (const float4*)(hidden + (size_t)(r0 + r) * DD);
        sp[r] = (const float4*)(wsub + (size_t)(r0 + r) * DD);
    }

    float acc[4][3];
    #pragma unroll
    for (int r = 0; r < 4; r++) { acc[r][0] = 0.f; acc[r][1] = 0.f; acc[r][2] = 0.f; }

    #pragma unroll
    for (int it = 0; it < 6; it++) {
        int i = it * 32 + lane;
        float4 w0 = e0[i], w1 = e1[i], w2 = e2[i];
        #pragma unroll
        for (int r = 0; r < 4; r++) {
            float4 x = hp[r][i];
            acc[r][0] = fmaf(x.x, w0.x, fmaf(x.y, w0.y, fmaf(x.z, w0.z, fmaf(x.w, w0.w, acc[r][0]))));
            acc[r][1] = fmaf(x.x, w1.x, fmaf(x.y, w1.y, fmaf(x.z, w1.z, fmaf(x.w, w1.w, acc[r][1]))));
            acc[r][2] = fmaf(x.x, w2.x, fmaf(x.y, w2.y, fmaf(x.z, w2.z, fmaf(x.w, w2.w, acc[r][2]))));
        }
    }
    #pragma unroll
    for (int it = 0; it < 6; it++) {
        int i = it * 32 + lane;
        int j = i + DD / 4;                       // second half of W_eff rows
        float4 w0 = e0[j], w1 = e1[j], w2 = e2[j];
        #pragma unroll
        for (int r = 0; r < 4; r++) {
            float4 x = sp[r][i];
            acc[r][0] = fmaf(x.x, w0.x, fmaf(x.y, w0.y, fmaf(x.z, w0.z, fmaf(x.w, w0.w, acc[r][0]))));
            acc[r][1] = fmaf(x.x, w1.x, fmaf(x.y, w1.y, fmaf(x.z, w1.z, fmaf(x.w, w1.w, acc[r][1]))));
            acc[r][2] = fmaf(x.x, w2.x, fmaf(x.y, w2.y, fmaf(x.z, w2.z, fmaf(x.w, w2.w, acc[r][2]))));
        }
    }
    #pragma unroll
    for (int r = 0; r < 4; r++) {
        #pragma unroll
        for (int k = 0; k < 3; k++) {
            float v = acc[r][k];
            #pragma unroll
            for (int o = 16; o; o >>= 1) v += __shfl_xor_sync(0xffffffffu, v, o);
            acc[r][k] = v;
        }
    }
    if (lane == 0) {
        #pragma unroll
        for (int r = 0; r < 4; r++) {
            float* o = g_logits + (size_t)(r0 + r) * KK;
            o[0] = acc[r][0] + g_beff[0];
            o[1] = acc[r][1] + g_beff[1];
            o[2] = acc[r][2] + g_beff[2];
        }
    }
}

// ---------------- CRF helpers ----------------
#define SENT (-1e38f)

__device__ __forceinline__ float lse3(float x, float y, float z) {
    float m = fmaxf(fmaxf(x, y), z);
    if (m < -1e30f) return SENT;     // guard: effectively -inf row, avoid NaN
    return m + __logf(__expf(x - m) + __expf(y - m) + __expf(z - m));
}

// packed tag-map composition: h(x) = f(g(x)); maps are 6-bit (2 bits per input tag)
__device__ __forceinline__ int mapcompose(int f, int g) {
    int h0 = (f >> (2 * (g & 3))) & 3;
    int h1 = (f >> (2 * ((g >> 2) & 3))) & 3;
    int h2 = (f >> (2 * ((g >> 4) & 3))) & 3;
    return h0 | (h1 << 2) | (h2 << 4);
}
#define IDMAP 0x24   // identity map: 0->0, 1->1, 2->2

// ---------------- kernel C: CRF ----------------
// one block (128 threads = 4 warps) per batch element
// warp0: parallel forward-LSE (semiring matrix scan) -> log_norm
// warp1: sequential viterbi forward (lane 0) + parallel traceback (map-composition scan)
// warp2: unary sum; warp3: binary sum
__global__ void __launch_bounds__(128) crf_kernel(const float* __restrict__ trans,
                                                  const int* __restrict__ tgt,
                                                  float* __restrict__ out,
                                                  int out_size) {
    __shared__ float sh_log[SS * KK];       // 6 KB
    __shared__ int sh_tgt[SS];              // 2 KB
    __shared__ int sh_bp[SS];               // 2 KB packed backpointers
    __shared__ int sh_seqlen;
    __shared__ int sh_init_tag;
    __shared__ float sh_lognorm, sh_unary, sh_binary;

    int b = blockIdx.x;
    int tid = threadIdx.x;
    int lane = tid & 31;
    int wid = tid >> 5;
    if (tid == 0) sh_seqlen = 0;

    for (int i = tid; i < SS; i += 128) sh_tgt[i] = tgt[b * SS + i];
    const float* lg = g_logits + (size_t)b * SS * KK;
    for (int i = tid; i < SS * KK; i += 128) sh_log[i] = lg[i];
    __syncthreads();

    // seq_len = count(obj_target >= 1)
    {
        int cnt = 0;
        for (int i = tid; i < SS; i += 128) cnt += (sh_tgt[i] >= 1);
        #pragma unroll
        for (int o = 16; o; o >>= 1) cnt += __shfl_xor_sync(0xffffffffu, cnt, o);
        if (lane == 0) atomicAdd(&sh_seqlen, cnt);
    }
    __syncthreads();
    int L = sh_seqlen;

    if (wid == 0) {
        // ---- forward LSE via (lse,+) semiring matrix scan ----
        int idx = L - 1;
        if (idx < 0) idx = 0;
        if (idx > SS - 1) idx = SS - 1;
        float t00 = trans[0], t01 = trans[1], t02 = trans[2];
        float t10 = trans[3], t11 = trans[4], t12 = trans[5];
        float t20 = trans[6], t21 = trans[7], t22 = trans[8];

        float p00 = 0.f,  p01 = SENT, p02 = SENT;
        float p10 = SENT, p11 = 0.f,  p12 = SENT;
        float p20 = SENT, p21 = SENT, p22 = 0.f;

        int tstart = 1 + lane * 16;
        for (int s = 0; s < 16; s++) {
            int t = tstart + s;
            if (t > idx) break;
            float l0 = sh_log[t * 3 + 0], l1 = sh_log[t * 3 + 1], l2 = sh_log[t * 3 + 2];
            float q00 = lse3(p00 + t00, p01 + t10, p02 + t20) + l0;
            float q01 = lse3(p00 + t01, p01 + t11, p02 + t21) + l1;
            float q02 = lse3(p00 + t02, p01 + t12, p02 + t22) + l2;
            float q10 = lse3(p10 + t00, p11 + t10, p12 + t20) + l0;
            float q11 = lse3(p10 + t01, p11 + t11, p12 + t21) + l1;
            float q12 = lse3(p10 + t02, p11 + t12, p12 + t22) + l2;
            float q20 = lse3(p20 + t00, p21 + t10, p22 + t20) + l0;
            float q21 = lse3(p20 + t01, p21 + t11, p22 + t21) + l1;
            float q22 = lse3(p20 + t02, p21 + t12, p22 + t22) + l2;
            p00 = q00; p01 = q01; p02 = q02;
            p10 = q10; p11 = q11; p12 = q12;
            p20 = q20; p21 = q21; p22 = q22;
        }
        // ordered binary-tree reduce: P_total = P_0 (x) P_1 (x) ... (x) P_31
        for (int d = 1; d < 32; d <<= 1) {
            float q00 = __shfl_down_sync(0xffffffffu, p00, d);
            float q01 = __shfl_down_sync(0xffffffffu, p01, d);
            float q02 = __shfl_down_sync(0xffffffffu, p02, d);
            float q10 = __shfl_down_sync(0xffffffffu, p10, d);
            float q11 = __shfl_down_sync(0xffffffffu, p11, d);
            float q12 = __shfl_down_sync(0xffffffffu, p12, d);
            float q20 = __shfl_down_sync(0xffffffffu, p20, d);
            float q21 = __shfl_down_sync(0xffffffffu, p21, d);
            float q22 = __shfl_down_sync(0xffffffffu, p22, d);
            if ((lane & (2 * d - 1)) == 0) {
                float r00 = lse3(p00 + q00, p01 + q10, p02 + q20);
                float r01 = lse3(p00 + q01, p01 + q11, p02 + q21);
                float r02 = lse3(p00 + q02, p01 + q12, p02 + q22);
                float r10 = lse3(p10 + q00, p11 + q10, p12 + q20);
                float r11 = lse3(p10 + q01, p11 + q11, p12 + q21);
                float r12 = lse3(p10 + q02, p11 + q12, p12 + q22);
                float r20 = lse3(p20 + q00, p21 + q10, p22 + q20);
                float r21 = lse3(p20 + q01, p21 + q11, p22 + q21);
                float r22 = lse3(p20 + q02, p21 + q12, p22 + q22);
                p00 = r00; p01 = r01; p02 = r02;
                p10 = r10; p11 = r11; p12 = r12;
                p20 = r20; p21 = r21; p22 = r22;
            }
        }
        if (lane == 0) {
            float a0 = sh_log[0], a1 = sh_log[1], a2 = sh_log[2];
            float f0 = lse3(a0 + p00, a1 + p10, a2 + p20);
            float f1 = lse3(a0 + p01, a1 + p11, a2 + p21);
            float f2 = lse3(a0 + p02, a1 + p12, a2 + p22);
            float ln = lse3(f0, f1, f2);
            sh_lognorm = (L <= 0) ? 0.0f : ln;
        }
    } else if (wid == 1) {
        // ---- sequential viterbi forward (exact, matches reference argmax order) ----
        if (lane == 0) {
            float t00 = trans[0], t01 = trans[1], t02 = trans[2];
            float t10 = trans[3], t11 = trans[4], t12 = trans[5];
            float t20 = trans[6], t21 = trans[7], t22 = trans[8];
            float a0 = sh_log[0], a1 = sh_log[1], a2 = sh_log[2];
            for (int t = 1; t < L; t++) {
                float l0 = sh_log[t * 3 + 0], l1 = sh_log[t * 3 + 1], l2 = sh_log[t * 3 + 2];
                float x0 = a0 + t00, x1 = a1 + t10, x2 = a2 + t20;
                float bst0 = x0; int bi0 = 0;
                if (x1 > bst0) { bst0 = x1; bi0 = 1; }
                if (x2 > bst0) { bst0 = x2; bi0 = 2; }
                float y0 = a0 + t01, y1 = a1 + t11, y2 = a2 + t21;
                float bst1 = y0; int bi1 = 0;
                if (y1 > bst1) { bst1 = y1; bi1 = 1; }
                if (y2 > bst1) { bst1 = y2; bi1 = 2; }
                float z0 = a0 + t02, z1 = a1 + t12, z2 = a2 + t22;
                float bst2 = z0; int bi2 = 0;
                if (z1 > bst2) { bst2 = z1; bi2 = 1; }
                if (z2 > bst2) { bst2 = z2; bi2 = 2; }
                sh_bp[t] = bi0 | (bi1 << 2) | (bi2 << 4);
                a0 = l0 + bst0; a1 = l1 + bst1; a2 = l2 + bst2;
            }
            int tag = 0;
            float bst = a0;
            if (a1 > bst) { bst = a1; tag = 1; }
            if (a2 > bst) { bst = a2; tag = 2; }
            sh_init_tag = (L > 0) ? tag : 0;
        }
        __syncwarp();
        // ---- parallel traceback: suffix scan over packed tag-maps (bit-exact) ----
        int init_tag = sh_init_tag;
        bool has_tags = (out_size >= BB * SS);
        // u = 510 - t (ascending u == descending t); lane owns u in [16*lane, 16*lane+15]
        int maps[16];
        int acc = IDMAP;
        #pragma unroll
        for (int s = 0; s < 16; s++) {
            int u = lane * 16 + s;
            int t = 510 - u;
            int m = IDMAP;
            if (u <= 510 && t <= L - 2) m = sh_bp[t + 1];
            maps[s] = m;
            acc = mapcompose(m, acc);
        }
        #pragma unroll
        for (int d = 1; d < 32; d <<= 1) {
            int peer = __shfl_up_sync(0xffffffffu, acc, d);
            if (lane >= d) acc = mapcompose(acc, peer);
        }
        int excl = __shfl_up_sync(0xffffffffu, acc, 1);
        if (lane == 0) excl = IDMAP;
        if (has_tags) {
            int g = excl;
            #pragma unroll
            for (int s = 0; s < 16; s++) {
                int u = lane * 16 + s;
                g = mapcompose(maps[s], g);
                if (u <= 510) {
                    int t = 510 - u;
                    int tagt = (t <= L - 1) ? ((g >> (2 * init_tag)) & 3) : 0;
                    out[b * SS + t] = (float)tagt;
                }
            }
            if (lane == 0) {
                int t511 = (L - 1 == SS - 1) ? init_tag : 0;
                out[b * SS + (SS - 1)] = (float)t511;
            }
        }
    } else if (wid == 2) {
        // ---- unary ----
        float u = 0.f;
        for (int s = lane; s < SS; s += 32)
            if (s < L) u += sh_log[s * 3 + sh_tgt[s]];
        #pragma unroll
        for (int o = 16; o; o >>= 1) u += __shfl_xor_sync(0xffffffffu, u, o);
        if (lane == 0) sh_unary = u;
    } else {
        // ---- binary ----
        float v = 0.f;
        for (int s = lane; s < SS - 1; s += 32)
            if (s < L - 1) v += trans[sh_tgt[s] * 3 + sh_tgt[s + 1]];
        #pragma unroll
        for (int o = 16; o; o >>= 1) v += __shfl_xor_sync(0xffffffffu, v, o);
        if (lane == 0) sh_binary = v;
    }
    __syncthreads();

    // ---- log_likelihood output ----
    bool has_tags = (out_size >= BB * SS);
    int ll_off = has_tags ? (BB * SS) : 0;
    if (out_size >= ll_off + BB && tid == 0) {
        out[ll_off + b] = sh_unary + sh_binary - sh_lognorm;
    }
    // if no tags section, nothing else to write
}

// ---------------- launch ----------------
extern "C" void kernel_launch(void* const* d_in, const int* in_sizes, int n_in,
                              void* d_out, int out_size) {
    const float *hidden = nullptr, *wsub = nullptr, *Wc = nullptr, *bc = nullptr;
    const float *Wd = nullptr, *bd = nullptr, *trans = nullptr;
    const int* tgt = nullptr;

    for (int i = 0; i < n_in; i++) {
        int sz = in_sizes[i];
        if (sz == BB * SS * DD) {
            if (!hidden) hidden = (const float*)d_in[i];
            else wsub = (const float*)d_in[i];
        } else if (sz == BB * SS) {
            tgt = (const int*)d_in[i];
        } else if (sz == TWOD * DD) {
            Wc = (const float*)d_in[i];
        } else if (sz == DD) {
            bc = (const float*)d_in[i];
        } else if (sz == DD * KK) {
            Wd = (const float*)d_in[i];
        } else if (sz == KK) {
            bd = (const float*)d_in[i];
        } else if (sz == KK * KK) {
            trans = (const float*)d_in[i];
        }
    }

    // A: fold W_cnn @ W_dense -> W_eff (1537 warps, float4 loads)
    weff_kernel<<<193, 256>>>(Wc, Wd, bc, bd);
    // B: logits, one warp per 4 rows: 4096 warps / 8 per block
    logits_kernel<<<(BB * SS) / 4 / 8, 256>>>(hidden, wsub);
    // C: CRF, one block per batch
    crf_kernel<<<BB, 128>>>(trans, tgt, (float*)d_out, out_size);
}

// round 3
// speedup vs baseline: 1.5007x; 1.0409x over previous
#include <cuda_runtime.h>
#include <math.h>

#define BB 32
#define SS 512
#define DD 768
#define KK 3
#define TWOD 1536

// ---------------- device scratch (no allocs allowed) ----------------
__device__ __align__(16) float g_WeffT[KK][TWOD];   // W_eff transposed: [k][d]
__device__ float g_beff[KK];
__device__ __align__(16) float g_logits[BB * SS * KK];

// ---------------- kernel A: W_eff = W_cnn @ W_dense, b_eff ----------------
// 4 warps/block, one warp per row. Wd staged in smem; Wc loads prefetched to regs.
__global__ void __launch_bounds__(128) weff_kernel(const float* __restrict__ Wc,
                                                   const float* __restrict__ Wd,
                                                   const float* __restrict__ bc,
                                                   const float* __restrict__ bd) {
    __shared__ float4 sWd[576];                 // 2304 floats = 9 KB
    int tid = threadIdx.x;
    for (int i = tid; i < 576; i += 128) sWd[i] = __ldg(((const float4*)Wd) + i);

    int gw = blockIdx.x * 4 + (tid >> 5);
    int lane = tid & 31;

    // prefetch the 6 Wc float4 loads BEFORE the barrier (independent of smem)
    float4 x[6];
    if (gw <= TWOD) {
        const float4* s4 = (const float4*)((gw < TWOD) ? (Wc + (size_t)gw * DD) : bc);
        #pragma unroll
        for (int it = 0; it < 6; it++) x[it] = __ldg(s4 + it * 32 + lane);
    }
    __syncthreads();
    if (gw > TWOD) return;

    float a0 = 0.f, a1 = 0.f, a2 = 0.f;
    #pragma unroll
    for (int it = 0; it < 6; it++) {
        int i = it * 32 + lane;
        float4 wA = sWd[i * 3 + 0];
        float4 wB = sWd[i * 3 + 1];
        float4 wC = sWd[i * 3 + 2];
        float4 v = x[it];
        a0 = fmaf(v.x, wA.x, a0); a1 = fmaf(v.x, wA.y, a1); a2 = fmaf(v.x, wA.z, a2);
        a0 = fmaf(v.y, wA.w, a0); a1 = fmaf(v.y, wB.x, a1); a2 = fmaf(v.y, wB.y, a2);
        a0 = fmaf(v.z, wB.z, a0); a1 = fmaf(v.z, wB.w, a1); a2 = fmaf(v.z, wC.x, a2);
        a0 = fmaf(v.w, wC.y, a0); a1 = fmaf(v.w, wC.z, a1); a2 = fmaf(v.w, wC.w, a2);
    }
    #pragma unroll
    for (int o = 16; o; o >>= 1) {
        a0 += __shfl_xor_sync(0xffffffffu, a0, o);
        a1 += __shfl_xor_sync(0xffffffffu, a1, o);
        a2 += __shfl_xor_sync(0xffffffffu, a2, o);
    }
    if (lane == 0) {
        if (gw < TWOD) {
            g_WeffT[0][gw] = a0;
            g_WeffT[1][gw] = a1;
            g_WeffT[2][gw] = a2;
        } else {
            g_beff[0] = a0 + bd[0];
            g_beff[1] = a1 + bd[1];
            g_beff[2] = a2 + bd[2];
        }
    }
}

// ---------------- kernel B: logits ----------------
// one warp per 4 (b,s) rows; 128-thread blocks for fine spread.
__global__ void __launch_bounds__(128) logits_kernel(const float* __restrict__ hidden,
                                                     const float* __restrict__ wsub) {
    int gw = blockIdx.x * 4 + (threadIdx.x >> 5);   // 0..4095
    int lane = threadIdx.x & 31;
    if (gw >= (BB * SS) / 4) return;
    int r0 = gw * 4;

    const float4* e0 = (const float4*)g_WeffT[0];
    const float4* e1 = (const float4*)g_WeffT[1];
    const float4* e2 = (const float4*)g_WeffT[2];
    const float4* hp[4];
    const float4* sp[4];
    #pragma unroll
    for (int r = 0; r < 4; r++) {
        hp[r] = (const float4*)(hidden + (size_t)(r0 + r) * DD);
        sp[r] = (const float4*)(wsub + (size_t)(r0 + r) * DD);
    }

    float acc[4][3];
    #pragma unroll
    for (int r = 0; r < 4; r++) { acc[r][0] = 0.f; acc[r][1] = 0.f; acc[r][2] = 0.f; }

    #pragma unroll
    for (int it = 0; it < 6; it++) {
        int i = it * 32 + lane;
        // issue all loads up front (independent)
        float4 xx[4];
        #pragma unroll
        for (int r = 0; r < 4; r++) xx[r] = __ldg(hp[r] + i);
        float4 w0 = __ldg(e0 + i), w1 = __ldg(e1 + i), w2 = __ldg(e2 + i);
        #pragma unroll
        for (int r = 0; r < 4; r++) {
            float4 x = xx[r];
            acc[r][0] = fmaf(x.x, w0.x, fmaf(x.y, w0.y, fmaf(x.z, w0.z, fmaf(x.w, w0.w, acc[r][0]))));
            acc[r][1] = fmaf(x.x, w1.x, fmaf(x.y, w1.y, fmaf(x.z, w1.z, fmaf(x.w, w1.w, acc[r][1]))));
            acc[r][2] = fmaf(x.x, w2.x, fmaf(x.y, w2.y, fmaf(x.z, w2.z, fmaf(x.w, w2.w, acc[r][2]))));
        }
    }
    #pragma unroll
    for (int it = 0; it < 6; it++) {
        int i = it * 32 + lane;
        int j = i + DD / 4;
        float4 xx[4];
        #pragma unroll
        for (int r = 0; r < 4; r++) xx[r] = __ldg(sp[r] + i);
        float4 w0 = __ldg(e0 + j), w1 = __ldg(e1 + j), w2 = __ldg(e2 + j);
        #pragma unroll
        for (int r = 0; r < 4; r++) {
            float4 x = xx[r];
            acc[r][0] = fmaf(x.x, w0.x, fmaf(x.y, w0.y, fmaf(x.z, w0.z, fmaf(x.w, w0.w, acc[r][0]))));
            acc[r][1] = fmaf(x.x, w1.x, fmaf(x.y, w1.y, fmaf(x.z, w1.z, fmaf(x.w, w1.w, acc[r][1]))));
            acc[r][2] = fmaf(x.x, w2.x, fmaf(x.y, w2.y, fmaf(x.z, w2.z, fmaf(x.w, w2.w, acc[r][2]))));
        }
    }
    #pragma unroll
    for (int r = 0; r < 4; r++) {
        #pragma unroll
        for (int k = 0; k < 3; k++) {
            float v = acc[r][k];
            #pragma unroll
            for (int o = 16; o; o >>= 1) v += __shfl_xor_sync(0xffffffffu, v, o);
            acc[r][k] = v;
        }
    }
    if (lane == 0) {
        #pragma unroll
        for (int r = 0; r < 4; r++) {
            float* o = g_logits + (size_t)(r0 + r) * KK;
            o[0] = acc[r][0] + g_beff[0];
            o[1] = acc[r][1] + g_beff[1];
            o[2] = acc[r][2] + g_beff[2];
        }
    }
}

// ---------------- CRF helpers ----------------
#define SENT (-1e38f)

__device__ __forceinline__ float lse3(float x, float y, float z) {
    float m = fmaxf(fmaxf(x, y), z);
    if (m < -1e30f) return SENT;     // effectively -inf row, avoid NaN
    return m + __logf(__expf(x - m) + __expf(y - m) + __expf(z - m));
}

// packed tag-map composition: h(x) = f(g(x)); maps are 6-bit (2 bits per input tag)
__device__ __forceinline__ int mapcompose(int f, int g) {
    int h0 = (f >> (2 * (g & 3))) & 3;
    int h1 = (f >> (2 * ((g >> 2) & 3))) & 3;
    int h2 = (f >> (2 * ((g >> 4) & 3))) & 3;
    return h0 | (h1 << 2) | (h2 << 4);
}
#define IDMAP 0x24   // identity map

// ---------------- kernel C: CRF ----------------
// one block (128 threads = 4 warps) per batch element
__global__ void __launch_bounds__(128) crf_kernel(const float* __restrict__ trans,
                                                  const int* __restrict__ tgt,
                                                  float* __restrict__ out,
                                                  int out_size) {
    __shared__ float sh_log[SS * KK];
    __shared__ int sh_tgt[SS];
    __shared__ int sh_bp[SS];
    __shared__ int sh_seqlen;
    __shared__ int sh_init_tag;
    __shared__ float sh_lognorm, sh_unary, sh_binary;

    int b = blockIdx.x;
    int tid = threadIdx.x;
    int lane = tid & 31;
    int wid = tid >> 5;
    if (tid == 0) sh_seqlen = 0;

    for (int i = tid; i < SS; i += 128) sh_tgt[i] = tgt[b * SS + i];
    const float* lg = g_logits + (size_t)b * SS * KK;
    for (int i = tid; i < SS * KK; i += 128) sh_log[i] = lg[i];
    __syncthreads();

    {
        int cnt = 0;
        for (int i = tid; i < SS; i += 128) cnt += (sh_tgt[i] >= 1);
        #pragma unroll
        for (int o = 16; o; o >>= 1) cnt += __shfl_xor_sync(0xffffffffu, cnt, o);
        if (lane == 0) atomicAdd(&sh_seqlen, cnt);
    }
    __syncthreads();
    int L = sh_seqlen;

    if (wid == 0) {
        // ---- forward LSE via (lse,+) semiring matrix scan ----
        int idx = L - 1;
        if (idx < 0) idx = 0;
        if (idx > SS - 1) idx = SS - 1;
        float t00 = trans[0], t01 = trans[1], t02 = trans[2];
        float t10 = trans[3], t11 = trans[4], t12 = trans[5];
        float t20 = trans[6], t21 = trans[7], t22 = trans[8];

        float p00 = 0.f,  p01 = SENT, p02 = SENT;
        float p10 = SENT, p11 = 0.f,  p12 = SENT;
        float p20 = SENT, p21 = SENT, p22 = 0.f;

        int tstart = 1 + lane * 16;
        for (int s = 0; s < 16; s++) {
            int t = tstart + s;
            if (t > idx) break;
            float l0 = sh_log[t * 3 + 0], l1 = sh_log[t * 3 + 1], l2 = sh_log[t * 3 + 2];
            float q00 = lse3(p00 + t00, p01 + t10, p02 + t20) + l0;
            float q01 = lse3(p00 + t01, p01 + t11, p02 + t21) + l1;
            float q02 = lse3(p00 + t02, p01 + t12, p02 + t22) + l2;
            float q10 = lse3(p10 + t00, p11 + t10, p12 + t20) + l0;
            float q11 = lse3(p10 + t01, p11 + t11, p12 + t21) + l1;
            float q12 = lse3(p10 + t02, p11 + t12, p12 + t22) + l2;
            float q20 = lse3(p20 + t00, p21 + t10, p22 + t20) + l0;
            float q21 = lse3(p20 + t01, p21 + t11, p22 + t21) + l1;
            float q22 = lse3(p20 + t02, p21 + t12, p22 + t22) + l2;
            p00 = q00; p01 = q01; p02 = q02;
            p10 = q10; p11 = q11; p12 = q12;
            p20 = q20; p21 = q21; p22 = q22;
        }
        for (int d = 1; d < 32; d <<= 1) {
            float q00 = __shfl_down_sync(0xffffffffu, p00, d);
            float q01 = __shfl_down_sync(0xffffffffu, p01, d);
            float q02 = __shfl_down_sync(0xffffffffu, p02, d);
            float q10 = __shfl_down_sync(0xffffffffu, p10, d);
            float q11 = __shfl_down_sync(0xffffffffu, p11, d);
            float q12 = __shfl_down_sync(0xffffffffu, p12, d);
            float q20 = __shfl_down_sync(0xffffffffu, p20, d);
            float q21 = __shfl_down_sync(0xffffffffu, p21, d);
            float q22 = __shfl_down_sync(0xffffffffu, p22, d);
            if ((lane & (2 * d - 1)) == 0) {
                float r00 = lse3(p00 + q00, p01 + q10, p02 + q20);
                float r01 = lse3(p00 + q01, p01 + q11, p02 + q21);
                float r02 = lse3(p00 + q02, p01 + q12, p02 + q22);
                float r10 = lse3(p10 + q00, p11 + q10, p12 + q20);
                float r11 = lse3(p10 + q01, p11 + q11, p12 + q21);
                float r12 = lse3(p10 + q02, p11 + q12, p12 + q22);
                float r20 = lse3(p20 + q00, p21 + q10, p22 + q20);
                float r21 = lse3(p20 + q01, p21 + q11, p22 + q21);
                float r22 = lse3(p20 + q02, p21 + q12, p22 + q22);
                p00 = r00; p01 = r01; p02 = r02;
                p10 = r10; p11 = r11; p12 = r12;
                p20 = r20; p21 = r21; p22 = r22;
            }
        }
        if (lane == 0) {
            float a0 = sh_log[0], a1 = sh_log[1], a2 = sh_log[2];
            float f0 = lse3(a0 + p00, a1 + p10, a2 + p20);
            float f1 = lse3(a0 + p01, a1 + p11, a2 + p21);
            float f2 = lse3(a0 + p02, a1 + p12, a2 + p22);
            float ln = lse3(f0, f1, f2);
            sh_lognorm = (L <= 0) ? 0.0f : ln;
        }
    } else if (wid == 1) {
        // ---- sequential viterbi forward (bit-exact order) with logits prefetch ----
        if (lane == 0) {
            float t00 = trans[0], t01 = trans[1], t02 = trans[2];
            float t10 = trans[3], t11 = trans[4], t12 = trans[5];
            float t20 = trans[6], t21 = trans[7], t22 = trans[8];
            float a0 = sh_log[0], a1 = sh_log[1], a2 = sh_log[2];
            float l0n = sh_log[3], l1n = sh_log[4], l2n = sh_log[5];
            for (int t = 1; t < L; t++) {
                float l0 = l0n, l1 = l1n, l2 = l2n;
                int tn = (t + 1 < SS - 1) ? (t + 1) : (SS - 1);   // clamp, branch-free
                l0n = sh_log[tn * 3 + 0]; l1n = sh_log[tn * 3 + 1]; l2n = sh_log[tn * 3 + 2];
                float x0 = a0 + t00, x1 = a1 + t10, x2 = a2 + t20;
                float bst0 = x0; int bi0 = 0;
                if (x1 > bst0) { bst0 = x1; bi0 = 1; }
                if (x2 > bst0) { bst0 = x2; bi0 = 2; }
                float y0 = a0 + t01, y1 = a1 + t11, y2 = a2 + t21;
                float bst1 = y0; int bi1 = 0;
                if (y1 > bst1) { bst1 = y1; bi1 = 1; }
                if (y2 > bst1) { bst1 = y2; bi1 = 2; }
                float z0 = a0 + t02, z1 = a1 + t12, z2 = a2 + t22;
                float bst2 = z0; int bi2 = 0;
                if (z1 > bst2) { bst2 = z1; bi2 = 1; }
                if (z2 > bst2) { bst2 = z2; bi2 = 2; }
                sh_bp[t] = bi0 | (bi1 << 2) | (bi2 << 4);
                a0 = l0 + bst0; a1 = l1 + bst1; a2 = l2 + bst2;
            }
            int tag = 0;
            float bst = a0;
            if (a1 > bst) { bst = a1; tag = 1; }
            if (a2 > bst) { bst = a2; tag = 2; }
            sh_init_tag = (L > 0) ? tag : 0;
        }
        __syncwarp();
        // ---- parallel traceback: suffix scan over packed tag-maps (bit-exact) ----
        int init_tag = sh_init_tag;
        bool has_tags = (out_size >= BB * SS);
        int maps[16];
        int acc = IDMAP;
        #pragma unroll
        for (int s = 0; s < 16; s++) {
            int u = lane * 16 + s;
            int t = 510 - u;
            int m = IDMAP;
            if (u <= 510 && t <= L - 2) m = sh_bp[t + 1];
            maps[s] = m;
            acc = mapcompose(m, acc);
        }
        #pragma unroll
        for (int d = 1; d < 32; d <<= 1) {
            int peer = __shfl_up_sync(0xffffffffu, acc, d);
            if (lane >= d) acc = mapcompose(acc, peer);
        }
        int excl = __shfl_up_sync(0xffffffffu, acc, 1);
        if (lane == 0) excl = IDMAP;
        if (has_tags) {
            int g = excl;
            #pragma unroll
            for (int s = 0; s < 16; s++) {
                int u = lane * 16 + s;
                g = mapcompose(maps[s], g);
                if (u <= 510) {
                    int t = 510 - u;
                    int tagt = (t <= L - 1) ? ((g >> (2 * init_tag)) & 3) : 0;
                    out[b * SS + t] = (float)tagt;
                }
            }
            if (lane == 0) {
                int t511 = (L - 1 == SS - 1) ? init_tag : 0;
                out[b * SS + (SS - 1)] = (float)t511;
            }
        }
    } else if (wid == 2) {
        float u = 0.f;
        for (int s = lane; s < SS; s += 32)
            if (s < L) u += sh_log[s * 3 + sh_tgt[s]];
        #pragma unroll
        for (int o = 16; o; o >>= 1) u += __shfl_xor_sync(0xffffffffu, u, o);
        if (lane == 0) sh_unary = u;
    } else {
        float v = 0.f;
        for (int s = lane; s < SS - 1; s += 32)
            if (s < L - 1) v += trans[sh_tgt[s] * 3 + sh_tgt[s + 1]];
        #pragma unroll
        for (int o = 16; o; o >>= 1) v += __shfl_xor_sync(0xffffffffu, v, o);
        if (lane == 0) sh_binary = v;
    }
    __syncthreads();

    bool has_tags = (out_size >= BB * SS);
    int ll_off = has_tags ? (BB * SS) : 0;
    if (out_size >= ll_off + BB && tid == 0) {
        out[ll_off + b] = sh_unary + sh_binary - sh_lognorm;
    }
}

// ---------------- launch ----------------
extern "C" void kernel_launch(void* const* d_in, const int* in_sizes, int n_in,
                              void* d_out, int out_size) {
    const float *hidden = nullptr, *wsub = nullptr, *Wc = nullptr, *bc = nullptr;
    const float *Wd = nullptr, *bd = nullptr, *trans = nullptr;
    const int* tgt = nullptr;

    for (int i = 0; i < n_in; i++) {
        int sz = in_sizes[i];
        if (sz == BB * SS * DD) {
            if (!hidden) hidden = (const float*)d_in[i];
            else wsub = (const float*)d_in[i];
        } else if (sz == BB * SS) {
            tgt = (const int*)d_in[i];
        } else if (sz == TWOD * DD) {
            Wc = (const float*)d_in[i];
        } else if (sz == DD) {
            bc = (const float*)d_in[i];
        } else if (sz == DD * KK) {
            Wd = (const float*)d_in[i];
        } else if (sz == KK) {
            bd = (const float*)d_in[i];
        } else if (sz == KK * KK) {
            trans = (const float*)d_in[i];
        }
    }

    // A: fold W_cnn @ W_dense -> W_eff (385 blocks x 4 warps, Wd in smem)
    weff_kernel<<<(TWOD + 4) / 4, 128>>>(Wc, Wd, bc, bd);
    // B: logits, one warp per 4 rows: 1024 blocks x 4 warps
    logits_kernel<<<(BB * SS) / 16, 128>>>(hidden, wsub);
    // C: CRF, one block per batch
    crf_kernel<<<BB, 128>>>(trans, tgt, (float*)d_out, out_size);
}